// round 1
// baseline (speedup 1.0000x reference)
#include <cuda_runtime.h>

#define TT 128   // decodelen
#define BB 512   // batch
#define EE 128   // entity size
#define EV 8     // event length

__device__ float g_Qk[EE * EE];   // g_Qk[k*EE + j] = exp(trans[j][k] - mt[j])
__device__ float g_mt[EE];        // row maxes of transitions
__device__ float g_partial[BB];   // per-batch alpha partial sums

// ---------------------------------------------------------------------------
// helpers
// ---------------------------------------------------------------------------
__device__ __forceinline__ void ffma2(unsigned long long &d,
                                      unsigned long long a,
                                      unsigned long long b) {
    asm("fma.rn.f32x2 %0, %1, %2, %0;" : "+l"(d) : "l"(a), "l"(b));
}

__device__ __forceinline__ float pairsum(unsigned long long a) {
    return __uint_as_float((unsigned)a) + __uint_as_float((unsigned)(a >> 32));
}

__device__ __forceinline__ float wredmax(float v) {
#pragma unroll
    for (int o = 16; o; o >>= 1) v = fmaxf(v, __shfl_xor_sync(0xffffffffu, v, o));
    return v;
}

__device__ __forceinline__ float wredsum(float v) {
#pragma unroll
    for (int o = 16; o; o >>= 1) v += __shfl_xor_sync(0xffffffffu, v, o);
    return v;
}

// ---------------------------------------------------------------------------
// prep: mt[j] = max_k trans[j][k];  Qk[k][j] = exp(trans[j][k] - mt[j])
// grid: EE blocks (one per j), EE threads (one per k)
// ---------------------------------------------------------------------------
__global__ void prep_kernel(const float* __restrict__ trans) {
    int j = blockIdx.x, k = threadIdx.x;
    float v = trans[j * EE + k];
    float m = wredmax(v);
    __shared__ float wm[4];
    if ((k & 31) == 0) wm[k >> 5] = m;
    __syncthreads();
    m = fmaxf(fmaxf(wm[0], wm[1]), fmaxf(wm[2], wm[3]));
    if (k == 0) g_mt[j] = m;
    g_Qk[k * EE + j] = __expf(v - m);
}

// ---------------------------------------------------------------------------
// main CRF forward: one block per 2 batch rows, 128 threads (thread j owns
// output tag j). Q row j lives in 128 registers as 64 packed f32x2 pairs.
// ---------------------------------------------------------------------------
__global__ void __launch_bounds__(128, 2)
crf_kernel(const float* __restrict__ feats, const float* __restrict__ trans) {
    const int b0 = blockIdx.x * 2, b1 = b0 + 1;
    const int j = threadIdx.x, lane = j & 31, wid = j >> 5;

    __shared__ __align__(16) float P0[EE];
    __shared__ __align__(16) float P1[EE];
    __shared__ float red0[4], red1[4];

    // Load Q row j, packed (Q[j][2i] in low word, Q[j][2i+1] in high word)
    unsigned long long q[64];
#pragma unroll
    for (int i = 0; i < 64; i++) {
        unsigned lo = __float_as_uint(g_Qk[(2 * i) * EE + j]);
        unsigned hi = __float_as_uint(g_Qk[(2 * i + 1) * EE + j]);
        q[i] = ((unsigned long long)hi << 32) | (unsigned long long)lo;
    }
    const float mtj = g_mt[j];
    const float tlj = trans[(EE - 1) * EE + j];   // transitions[-1][j]

    float fv0 = (b0 == 0) ? 0.0f : -10000.0f;    // init_alphas: batch-0 row = 0
    float fv1 = -10000.0f;                        // b1 >= 1 always
    float al0 = 0.0f, al1 = 0.0f;                 // thread 0's copy is used

    const float* fp0 = feats + (size_t)b0 * EE + j;
    const float* fp1 = feats + (size_t)b1 * EE + j;
    // prefetch feat for t=1 (t=0 is skipped entirely: no boundary, no update)
    float f0 = fp0[(size_t)BB * EE];
    float f1 = fp1[(size_t)BB * EE];

    for (int t = 0; t < TT; t++) {
        if ((t & (EV - 1)) == 0) {
            if (t) {
                // event boundary: alpha += lse_k(fv + trans[-1])  (fv unchanged)
                float v0 = fv0 + tlj, v1 = fv1 + tlj;
                float m0 = wredmax(v0), m1 = wredmax(v1);
                if (lane == 0) { red0[wid] = m0; red1[wid] = m1; }
                __syncthreads();
                m0 = fmaxf(fmaxf(red0[0], red0[1]), fmaxf(red0[2], red0[3]));
                m1 = fmaxf(fmaxf(red1[0], red1[1]), fmaxf(red1[2], red1[3]));
                __syncthreads();
                float e0 = wredsum(__expf(v0 - m0));
                float e1 = wredsum(__expf(v1 - m1));
                if (lane == 0) { red0[wid] = e0; red1[wid] = e1; }
                __syncthreads();
                if (j == 0) {
                    al0 += m0 + __logf(red0[0] + red0[1] + red0[2] + red0[3]);
                    al1 += m1 + __logf(red1[0] + red1[1] + red1[2] + red1[3]);
                }
                __syncthreads();
            }
            continue;   // no DP update on boundary steps (feat[t] unused)
        }

        // ---- DP update step ----
        float x0 = fv0 + f0, x1 = fv1 + f1;
        {   // prefetch feat of the next UPDATE step (skip boundary t's)
            int tn = t + 1;
            if ((tn & (EV - 1)) == 0) tn++;
            if (tn < TT) {
                size_t off = (size_t)tn * BB * EE;
                f0 = fp0[off];
                f1 = fp1[off];
            }
        }
        float m0 = wredmax(x0), m1 = wredmax(x1);
        if (lane == 0) { red0[wid] = m0; red1[wid] = m1; }
        __syncthreads();
        m0 = fmaxf(fmaxf(red0[0], red0[1]), fmaxf(red0[2], red0[3]));
        m1 = fmaxf(fmaxf(red1[0], red1[1]), fmaxf(red1[2], red1[3]));
        P0[j] = __expf(x0 - m0);
        P1[j] = __expf(x1 - m1);
        __syncthreads();

        // matvec: y[j] = sum_k Q[j][k] * P[k]   (packed f32x2, 2 batches)
        const ulonglong2* p0 = (const ulonglong2*)P0;
        const ulonglong2* p1 = (const ulonglong2*)P1;
        unsigned long long a00 = 0, a01 = 0, a10 = 0, a11 = 0;
#pragma unroll
        for (int i = 0; i < 32; i++) {
            ulonglong2 u0 = p0[i];
            ulonglong2 u1 = p1[i];
            ffma2(a00, q[2 * i],     u0.x);
            ffma2(a01, q[2 * i + 1], u0.y);
            ffma2(a10, q[2 * i],     u1.x);
            ffma2(a11, q[2 * i + 1], u1.y);
        }
        float y0 = pairsum(a00) + pairsum(a01);
        float y1 = pairsum(a10) + pairsum(a11);
        fv0 = m0 + mtj + __logf(y0);
        fv1 = m1 + mtj + __logf(y1);
    }

    // terminal accumulation
    {
        float v0 = fv0 + tlj, v1 = fv1 + tlj;
        float m0 = wredmax(v0), m1 = wredmax(v1);
        if (lane == 0) { red0[wid] = m0; red1[wid] = m1; }
        __syncthreads();
        m0 = fmaxf(fmaxf(red0[0], red0[1]), fmaxf(red0[2], red0[3]));
        m1 = fmaxf(fmaxf(red1[0], red1[1]), fmaxf(red1[2], red1[3]));
        __syncthreads();
        float e0 = wredsum(__expf(v0 - m0));
        float e1 = wredsum(__expf(v1 - m1));
        if (lane == 0) { red0[wid] = e0; red1[wid] = e1; }
        __syncthreads();
        if (j == 0) {
            al0 += m0 + __logf(red0[0] + red0[1] + red0[2] + red0[3]);
            al1 += m1 + __logf(red1[0] + red1[1] + red1[2] + red1[3]);
            g_partial[b0] = al0;
            g_partial[b1] = al1;
        }
    }
}

// ---------------------------------------------------------------------------
// final: out = sum_b partial[b] / (B * n_events)
// ---------------------------------------------------------------------------
__global__ void reduce_kernel(float* __restrict__ out) {
    int i = threadIdx.x;          // 512 threads
    float v = g_partial[i];
    v = wredsum(v);
    __shared__ float s[16];
    if ((i & 31) == 0) s[i >> 5] = v;
    __syncthreads();
    if (i == 0) {
        float tot = 0.0f;
#pragma unroll
        for (int w = 0; w < 16; w++) tot += s[w];
        out[0] = tot * (1.0f / (float)(BB * (TT / EV)));
    }
}

// ---------------------------------------------------------------------------
extern "C" void kernel_launch(void* const* d_in, const int* in_sizes, int n_in,
                              void* d_out, int out_size) {
    const float* feats = (const float*)d_in[0];
    const float* trans = (const float*)d_in[1];
    // defensive: identify transitions by its element count (EE*EE vs TT*BB*EE)
    if (n_in >= 2 && in_sizes[0] == EE * EE) {
        feats = (const float*)d_in[1];
        trans = (const float*)d_in[0];
    }
    prep_kernel<<<EE, EE>>>(trans);
    crf_kernel<<<BB / 2, EE>>>(feats, trans);
    reduce_kernel<<<1, BB>>>((float*)d_out);
}

// round 4
// speedup vs baseline: 1.0683x; 1.0683x over previous
#include <cuda_runtime.h>

#define TT 128   // decodelen
#define BB 512   // batch
#define EE 128   // entity size
#define NEVT 16  // number of lse accumulations (15 boundaries + terminal)
#define L2E 1.4426950408889634f
#define LN2 0.6931471805599453f

__device__ float g_partial[BB];   // per-batch alpha partial sums (natural log units)

// ---------------------------------------------------------------------------
// helpers
// ---------------------------------------------------------------------------
__device__ __forceinline__ void ffma2(unsigned long long &d,
                                      unsigned long long a,
                                      unsigned long long b) {
    asm("fma.rn.f32x2 %0, %1, %2, %0;" : "+l"(d) : "l"(a), "l"(b));
}
__device__ __forceinline__ void fadd2(unsigned long long &d, unsigned long long a) {
    asm("add.rn.f32x2 %0, %0, %1;" : "+l"(d) : "l"(a));
}
__device__ __forceinline__ unsigned long long pack2(float lo, float hi) {
    unsigned long long r;
    asm("mov.b64 %0, {%1, %2};" : "=l"(r) : "f"(lo), "f"(hi));
    return r;
}
__device__ __forceinline__ float pairsum(unsigned long long a) {
    float lo, hi;
    asm("mov.b64 {%0, %1}, %2;" : "=f"(lo), "=f"(hi) : "l"(a));
    return lo + hi;
}
__device__ __forceinline__ float ex2(float x) {   // 2^x, MUFU
    float r; asm("ex2.approx.ftz.f32 %0, %1;" : "=f"(r) : "f"(x)); return r;
}
__device__ __forceinline__ float lg2(float x) {   // log2 x, MUFU
    float r; asm("lg2.approx.ftz.f32 %0, %1;" : "=f"(r) : "f"(x)); return r;
}
__device__ __forceinline__ float wmax(float v) {  // warp max (butterfly)
#pragma unroll
    for (int o = 16; o; o >>= 1) v = fmaxf(v, __shfl_xor_sync(0xffffffffu, v, o));
    return v;
}
__device__ __forceinline__ float wsum(float v) {  // warp sum (rare path)
#pragma unroll
    for (int o = 16; o; o >>= 1) v += __shfl_xor_sync(0xffffffffu, v, o);
    return v;
}

// ---------------------------------------------------------------------------
// main CRF forward. One block per 2 batch rows, 128 threads (thread j owns
// output tag j). Q row j (log2-domain) lives in 128 regs as 64 f32x2 pairs.
// All fv/x values are scaled by log2(e): exp -> EX2, log -> LG2, no mults.
// Normalizer G is a lagged (2-step) global max estimate -> exact lse math,
// no max-reduction on the critical path, ONE barrier per step.
// ---------------------------------------------------------------------------
__global__ void __launch_bounds__(128, 2)
crf_kernel(const float* __restrict__ feats, const float* __restrict__ trans) {
    const int b0 = blockIdx.x * 2;
    const int j = threadIdx.x, lane = j & 31, wid = j >> 5;

    // P buffers, interleaved: for pair i (k=2i,2i+1):
    //   [4i]=P0[2i] [4i+1]=P0[2i+1] [4i+2]=P1[2i] [4i+3]=P1[2i+1]
    __shared__ __align__(16) float PI[2][EE * 2];
    __shared__ __align__(16) float wmbuf[2][2][4];     // [parity][batch][warp]
    __shared__ float bmv[2][NEVT][4], bsv[2][NEVT][4]; // boundary partials

    // ---- fused prep: build my Q row (log2 domain) ----
    const float4* row = (const float4*)(trans + j * EE);
    float m = -3.4e38f;
#pragma unroll
    for (int i = 0; i < 32; i++) {
        float4 v = row[i];
        m = fmaxf(m, fmaxf(fmaxf(v.x, v.y), fmaxf(v.z, v.w)));
    }
    unsigned long long q[64];
#pragma unroll
    for (int i = 0; i < 32; i++) {
        float4 v = row[i];   // L1 hit (second pass over same 512B row)
        q[2 * i]     = pack2(ex2((v.x - m) * L2E), ex2((v.y - m) * L2E));
        q[2 * i + 1] = pack2(ex2((v.z - m) * L2E), ex2((v.w - m) * L2E));
    }
    const float mt2 = m * L2E;
    const float tl2 = trans[(EE - 1) * EE + j] * L2E;  // transitions[-1][j], log2 units

    float fv0 = (b0 == 0) ? 0.0f : (-10000.0f * L2E); // init (batch-0 row zeroed)
    float fv1 = -10000.0f * L2E;
    float G0 = fv0, G1 = fv1;                          // normalizer for update u=0
    float G0n = fv0, G1n = fv1;                        // for u=1 (refreshed in-loop)
    if (lane == 0) { wmbuf[1][0][wid] = fv0; wmbuf[1][1][wid] = fv1; }
    __syncthreads();

    const size_t bstride = (size_t)BB * EE;
    const float* fp0 = feats + (size_t)b0 * EE + j;
    const float* fp1 = fp0 + EE;
    float f0 = fp0[bstride];   // feat[t=1]
    float f1 = fp1[bstride];

    int u = 0;                 // update counter (0..111)
#pragma unroll 1
    for (int e = 0; e < NEVT; e++) {
        if (e > 0) {
            // event boundary: per-warp lse partials of fv + trans[-1]; deferred combine
            float v0 = fv0 + tl2, v1 = fv1 + tl2;
            float m0 = wmax(v0), m1 = wmax(v1);
            float s0 = wsum(ex2(v0 - m0)), s1 = wsum(ex2(v1 - m1));
            if (lane == 0) {
                bmv[0][e - 1][wid] = m0; bsv[0][e - 1][wid] = s0;
                bmv[1][e - 1][wid] = m1; bsv[1][e - 1][wid] = s1;
            }
        }
#pragma unroll 1
        for (int s = 1; s <= 7; s++, u++) {
            float* PIw = &PI[u & 1][(j >> 1) * 4 + (j & 1)];
            float x0 = fmaf(f0, L2E, fv0);
            float x1 = fmaf(f1, L2E, fv1);
            PIw[0] = ex2(x0 - G0);
            PIw[2] = ex2(x1 - G1);
            __syncthreads();
            // refresh next-step normalizer from warp maxes written at u-1
            {
                const float4 w0 = *(const float4*)wmbuf[(u + 1) & 1][0];
                const float4 w1 = *(const float4*)wmbuf[(u + 1) & 1][1];
                G0n = fmaxf(fmaxf(w0.x, w0.y), fmaxf(w0.z, w0.w));
                G1n = fmaxf(fmaxf(w1.x, w1.y), fmaxf(w1.z, w1.w));
            }
            // prefetch next update's feat (skip boundary timestep)
            {
                int t  = e * 8 + s;
                int tn = (s == 7) ? t + 9 : t + 1;
                if (tn < TT) {
                    size_t off = (size_t)tn * bstride;
                    f0 = fp0[off]; f1 = fp1[off];
                }
            }
            // matvec: y[j] = sum_k Q[j][k] * P[k], both batches, 8 acc chains
            unsigned long long a00 = 0, a01 = 0, a02 = 0, a03 = 0;
            unsigned long long a10 = 0, a11 = 0, a12 = 0, a13 = 0;
            const ulonglong2* pp = (const ulonglong2*)PI[u & 1];
#pragma unroll
            for (int i = 0; i < 64; i += 4) {
                ulonglong2 u0 = pp[i],     u1 = pp[i + 1];
                ulonglong2 u2 = pp[i + 2], u3 = pp[i + 3];
                ffma2(a00, q[i],     u0.x);  ffma2(a10, q[i],     u0.y);
                ffma2(a01, q[i + 1], u1.x);  ffma2(a11, q[i + 1], u1.y);
                ffma2(a02, q[i + 2], u2.x);  ffma2(a12, q[i + 2], u2.y);
                ffma2(a03, q[i + 3], u3.x);  ffma2(a13, q[i + 3], u3.y);
            }
            fadd2(a00, a01); fadd2(a02, a03); fadd2(a00, a02);
            fadd2(a10, a11); fadd2(a12, a13); fadd2(a10, a12);
            fv0 = G0 + mt2 + lg2(pairsum(a00));
            fv1 = G1 + mt2 + lg2(pairsum(a10));
            // publish warp maxes of new fv (consumed as G two updates later;
            // the shuffle chain is off the critical path)
            float wx0 = wmax(fv0), wx1 = wmax(fv1);
            if (lane == 0) { wmbuf[u & 1][0][wid] = wx0; wmbuf[u & 1][1][wid] = wx1; }
            G0 = G0n; G1 = G1n;
        }
    }
    // terminal accumulation partials
    {
        float v0 = fv0 + tl2, v1 = fv1 + tl2;
        float m0 = wmax(v0), m1 = wmax(v1);
        float s0 = wsum(ex2(v0 - m0)), s1 = wsum(ex2(v1 - m1));
        if (lane == 0) {
            bmv[0][NEVT - 1][wid] = m0; bsv[0][NEVT - 1][wid] = s0;
            bmv[1][NEVT - 1][wid] = m1; bsv[1][NEVT - 1][wid] = s1;
        }
    }
    __syncthreads();
    // combine all deferred boundary partials: warp 0, lane = event + 16*batch
    if (j < 32) {
        int ev = j & 15, bt = j >> 4;
        float m0 = bmv[bt][ev][0], m1 = bmv[bt][ev][1];
        float m2 = bmv[bt][ev][2], m3 = bmv[bt][ev][3];
        float M = fmaxf(fmaxf(m0, m1), fmaxf(m2, m3));
        float ss = bsv[bt][ev][0] * ex2(m0 - M) + bsv[bt][ev][1] * ex2(m1 - M)
                 + bsv[bt][ev][2] * ex2(m2 - M) + bsv[bt][ev][3] * ex2(m3 - M);
        float l = M + lg2(ss);          // per-event lse, log2 units
#pragma unroll
        for (int o = 1; o < 16; o <<= 1) l += __shfl_xor_sync(0xffffffffu, l, o);
        if (ev == 0) g_partial[b0 + bt] = l * LN2;   // back to natural log
    }
}

// ---------------------------------------------------------------------------
// final: out = sum_b partial[b] / (B * n_events)
// ---------------------------------------------------------------------------
__global__ void reduce_kernel(float* __restrict__ out) {
    int i = threadIdx.x;          // 512 threads
    float v = g_partial[i];
    v = wsum(v);
    __shared__ float s[16];
    if ((i & 31) == 0) s[i >> 5] = v;
    __syncthreads();
    if (i == 0) {
        float tot = 0.0f;
#pragma unroll
        for (int w = 0; w < 16; w++) tot += s[w];
        out[0] = tot * (1.0f / (float)(BB * NEVT));
    }
}

// ---------------------------------------------------------------------------
extern "C" void kernel_launch(void* const* d_in, const int* in_sizes, int n_in,
                              void* d_out, int out_size) {
    const float* feats = (const float*)d_in[0];
    const float* trans = (const float*)d_in[1];
    if (n_in >= 2 && in_sizes[0] == EE * EE) {   // defensive order check
        feats = (const float*)d_in[1];
        trans = (const float*)d_in[0];
    }
    crf_kernel<<<BB / 2, EE>>>(feats, trans);
    reduce_kernel<<<1, BB>>>((float*)d_out);
}